// round 2
// baseline (speedup 1.0000x reference)
#include <cuda_runtime.h>
#include <cuda_bf16.h>

#define TW 32
#define TH 8
#define HW 34   // TW + 2 halo
#define HH 10   // TH + 2 halo

// Per-pixel transform stored in smem:
//   s_sh : silu(x)
//   w_sh[c] : the 4 nonzero cubic B-spline basis values
//   j_sh : cell index (base offset into padded weight table)
// Output(p) = sum over 9 neighbors n (feature f = kh*3+kw):
//   silu(x_n)*bw[f] + sum_c w_n[c] * swp[f][j_n + c]
__global__ __launch_bounds__(256)
void kan_conv_kernel(const float* __restrict__ x,
                     const float* __restrict__ bw,
                     const float* __restrict__ sw,
                     const float* __restrict__ ss,
                     float* __restrict__ out)
{
    __shared__ float s_sh[HH * HW];
    __shared__ float w_sh[4][HH * HW];
    __shared__ int   j_sh[HH * HW];
    __shared__ float swp[9][16];   // scaled spline weights, padded: index = basis_idx + 3, zeros outside [0,8)
    __shared__ float bwc[9];

    const int tx = threadIdx.x, ty = threadIdx.y;
    const int tid = ty * TW + tx;

    // --- preload + pre-scale weights ---
    if (tid < 9 * 16) {
        int f = tid >> 4, idx = tid & 15;
        float v = 0.f;
        int bi = idx - 3;
        if (bi >= 0 && bi < 8) v = sw[f * 8 + bi] * ss[f];
        swp[f][idx] = v;
    }
    if (tid < 9) bwc[tid] = bw[tid];

    const int img = blockIdx.z;                 // 0..B*C-1, each an independent 64x64 image
    const float* xi = x + img * 64 * 64;
    const int x0 = blockIdx.x * TW, y0 = blockIdx.y * TH;

    // --- halo load + per-pixel transform (340 pixels, 256 threads) ---
    for (int i = tid; i < HH * HW; i += 256) {
        int ly = i / HW, lx = i % HW;
        int gy = y0 + ly - 1, gx = x0 + lx - 1;
        float v = 0.f;                          // zero padding (bases at 0 are NONZERO, handled below)
        if (gy >= 0 && gy < 64 && gx >= 0 && gx < 64) v = xi[gy * 64 + gx];

        // SiLU
        s_sh[i] = v / (1.f + __expf(-v));

        // Cubic B-spline on uniform extended grid: knots t_i = -2.2 + 0.4*i, i=0..11
        // x in cell j ([t_j, t_{j+1})) -> nonzero bases j-3..j with standard uniform weights.
        float xc = (v + 2.2f) * 2.5f;           // (v - t0)/h
        int   j  = (int)floorf(xc);
        float u  = xc - (float)j;
        float w0, w1, w2, w3;
        if (j < 0 || j > 10) {                  // outside extended grid: all bases zero
            j = 0; w0 = w1 = w2 = w3 = 0.f;
        } else {
            float um = 1.f - u;
            float u2 = u * u, u3 = u2 * u;
            w0 = um * um * um            * (1.f / 6.f);   // B_{j-3}
            w1 = ( 3.f*u3 - 6.f*u2 + 4.f) * (1.f / 6.f);  // B_{j-2}
            w2 = (-3.f*u3 + 3.f*u2 + 3.f*u + 1.f) * (1.f / 6.f); // B_{j-1}
            w3 = u3                       * (1.f / 6.f);  // B_j
        }
        j_sh[i] = j;                            // padded table index = (j-3+c)+3 = j+c
        w_sh[0][i] = w0; w_sh[1][i] = w1; w_sh[2][i] = w2; w_sh[3][i] = w3;
    }
    __syncthreads();

    // --- 3x3 stencil accumulation ---
    float acc = 0.f;
    #pragma unroll
    for (int kh = 0; kh < 3; kh++) {
        #pragma unroll
        for (int kw = 0; kw < 3; kw++) {
            const int f = kh * 3 + kw;
            const int i = (ty + kh) * HW + (tx + kw);
            acc += s_sh[i] * bwc[f];
            const int j = j_sh[i];
            #pragma unroll
            for (int c = 0; c < 4; c++)
                acc += w_sh[c][i] * swp[f][j + c];
        }
    }
    out[img * 4096 + (y0 + ty) * 64 + (x0 + tx)] = acc;
}

extern "C" void kernel_launch(void* const* d_in, const int* in_sizes, int n_in,
                              void* d_out, int out_size) {
    const float* x  = (const float*)d_in[0];  // (8,32,64,64)
    const float* bw = (const float*)d_in[1];  // (1,9)
    const float* sw = (const float*)d_in[2];  // (1,9,8)
    const float* ss = (const float*)d_in[3];  // (1,9)
    float* out = (float*)d_out;

    dim3 block(TW, TH);                       // 256 threads
    dim3 grid(64 / TW, 64 / TH, 8 * 32);      // (2, 8, 256)
    kan_conv_kernel<<<grid, block>>>(x, bw, sw, ss, out);
}

// round 4
// speedup vs baseline: 1.2388x; 1.2388x over previous
#include <cuda_runtime.h>
#include <cuda_bf16.h>

#define TW 32
#define TH 8
#define HW 34          // TW + 2 halo
#define HH 10          // TH + 2 halo
#define NP (HH * HW)   // 340 halo pixels per tile

// KAN 3x3 conv, shared KANLinear(9->1), cubic B-spline on uniform grid.
// Pixel phase: per halo pixel compute v[f] = silu(x)*bw[f] + P_{f,cell(x)}(u),
// where P is the per-(feature,cell) cubic polynomial equivalent of the
// 4 nonzero uniform B-spline bases contracted with scaled spline weights.
// Output phase: o(y,x) = sum over 9 neighbors of v[f] -> 9 LDS + 8 adds.
__global__ __launch_bounds__(256)
void kan_conv_kernel(const float* __restrict__ x,
                     const float* __restrict__ bw,
                     const float* __restrict__ sw,
                     const float* __restrict__ ss,
                     float* __restrict__ out)
{
    __shared__ float4 poly[11 * 9];      // [cell j][feature f] cubic coeffs
    __shared__ float  v_sh[9][NP];       // per-pixel per-feature contribution

    const int tx = threadIdx.x, ty = threadIdx.y;
    const int tid = ty * TW + tx;

    const int img = blockIdx.z;          // 0..B*C-1, independent 64x64 images
    const float* xi = x + img * 4096;
    const int x0 = blockIdx.x * TW, y0 = blockIdx.y * TH;

    // --- base weights into registers (broadcast L1 hits) ---
    float bwr[9];
    #pragma unroll
    for (int f = 0; f < 9; f++) bwr[f] = __ldg(&bw[f]);

    // --- halo pixel loads into registers (overlap with poly build) ---
    float pv0 = 0.f, pv1 = 0.f;
    {
        int ly = tid / HW, lx = tid - ly * HW;
        int gy = y0 + ly - 1, gx = x0 + lx - 1;
        if (gy >= 0 && gy < 64 && gx >= 0 && gx < 64) pv0 = xi[gy * 64 + gx];
    }
    const int i1 = tid + 256;
    if (i1 < NP) {
        int ly = i1 / HW, lx = i1 - ly * HW;
        int gy = y0 + ly - 1, gx = x0 + lx - 1;
        if (gy >= 0 && gy < 64 && gx >= 0 && gx < 64) pv1 = xi[gy * 64 + gx];
    }

    // --- build polynomial table: 99 (cell, feature) entries ---
    // Uniform cubic basis weights in u (cell-local coordinate):
    //   w0=(1-u)^3/6, w1=(3u^3-6u^2+4)/6, w2=(-3u^3+3u^2+3u+1)/6, w3=u^3/6
    // contracted with W[c] = padded scaled spline weights -> cubic in u.
    if (tid < 99) {
        int j = tid / 9, f = tid - j * 9;      // j = 0..10 cell index
        float scale = __ldg(&ss[f]);
        float W[4];
        #pragma unroll
        for (int c = 0; c < 4; c++) {
            int bi = j + c - 3;                // coefficient index in [0,8)
            W[c] = (bi >= 0 && bi < 8) ? __ldg(&sw[f * 8 + bi]) * scale : 0.f;
        }
        const float S = 1.f / 6.f;
        float a0 = (W[0] + 4.f * W[1] + W[2]) * S;
        float a1 = (W[2] - W[0]) * 0.5f;
        float a2 = (W[0] - 2.f * W[1] + W[2]) * 0.5f;
        float a3 = (W[3] - W[0] + 3.f * (W[1] - W[2])) * S;
        poly[tid] = make_float4(a0, a1, a2, a3);
    }
    __syncthreads();

    // --- pixel phase: transform both halo pixels ---
    #pragma unroll
    for (int t = 0; t < 2; t++) {
        const int i = (t == 0) ? tid : i1;
        if (t == 1 && i >= NP) break;
        const float v = (t == 0) ? pv0 : pv1;

        // SiLU
        const float s = v * __frcp_rn(1.f + __expf(-v));

        // locate spline cell: knots t_i = -2.2 + 0.4*i
        const float xc = (v + 2.2f) * 2.5f;
        const float jf = floorf(xc);
        int   j = (int)jf;
        float u = xc - jf;
        const bool ok = (j >= 0) && (j <= 10);
        const float vf = ok ? 1.f : 0.f;
        if (!ok) j = 0;

        const float4* pj = &poly[j * 9];
        #pragma unroll
        for (int f = 0; f < 9; f++) {
            float4 a = pj[f];
            float sp = fmaf(fmaf(fmaf(a.w, u, a.z), u, a.y), u, a.x);
            v_sh[f][i] = fmaf(sp, vf, s * bwr[f]);
        }
    }
    __syncthreads();

    // --- output phase: 9-term neighbor sum ---
    float acc = 0.f;
    #pragma unroll
    for (int kh = 0; kh < 3; kh++) {
        #pragma unroll
        for (int kw = 0; kw < 3; kw++) {
            acc += v_sh[kh * 3 + kw][(ty + kh) * HW + (tx + kw)];
        }
    }
    out[img * 4096 + (y0 + ty) * 64 + (x0 + tx)] = acc;
}

extern "C" void kernel_launch(void* const* d_in, const int* in_sizes, int n_in,
                              void* d_out, int out_size) {
    const float* x  = (const float*)d_in[0];  // (8,32,64,64)
    const float* bw = (const float*)d_in[1];  // (1,9)
    const float* sw = (const float*)d_in[2];  // (1,9,8)
    const float* ss = (const float*)d_in[3];  // (1,9)
    float* out = (float*)d_out;

    dim3 block(TW, TH);                       // 256 threads
    dim3 grid(64 / TW, 64 / TH, 8 * 32);      // (2, 8, 256)
    kan_conv_kernel<<<grid, block>>>(x, bw, sw, ss, out);
}

// round 5
// speedup vs baseline: 1.6275x; 1.3137x over previous
#include <cuda_runtime.h>
#include <cuda_bf16.h>

#define R_ROWS 8              // output rows per warp-strip
#define NROWS  (R_ROWS + 2)   // pixel rows streamed (with vertical halo)

// KAN 3x3 conv, shared KANLinear(9->1), cubic B-spline on uniform grid.
// Warp-per-strip register-rolling design:
//  - lane l owns output columns (2l, 2l+1); warp covers the full 64-wide row.
//  - pixel rows stream downward; per pixel compute 9 per-feature values
//    v[f] = silu(x)*bw[f] + P_{f,cell(x)}(u) and accumulate directly into
//    3 rolling row-accumulators (rows r-1, r, r+1) per column.
//  - horizontal neighbor exchange via 6 warp shuffles per pixel row.
//  - padding pixels are x=0: silu=0, spline value Z[f] (cell j=5, u=0.5);
//    lane-edge shuffles are patched with Z, out-of-image rows use x=0.
__global__ __launch_bounds__(32)
void kan_conv_kernel(const float* __restrict__ x,
                     const float* __restrict__ bw,
                     const float* __restrict__ sw,
                     const float* __restrict__ ss,
                     float* __restrict__ out)
{
    __shared__ float4 poly[12 * 9];   // [cell j][feature f]; row j=11 is all zeros

    const int lane  = threadIdx.x;          // 0..31
    const int img   = blockIdx.x >> 3;      // 2048 blocks = 256 images x 8 strips
    const int strip = blockIdx.x & 7;
    const int y0    = strip * R_ROWS;

    // ---- build polynomial table (scaled spline weights -> cubic coeffs) ----
    // Uniform cubic B-spline bases contracted with padded weights W[c]:
    //   a0=(W0+4W1+W2)/6, a1=(W2-W0)/2, a2=(W0-2W1+W2)/2, a3=(W3-W0+3(W1-W2))/6
    for (int t = lane; t < 108; t += 32) {
        int j = t / 9, f = t - j * 9;
        float4 v = make_float4(0.f, 0.f, 0.f, 0.f);
        if (j < 11) {
            float scale = __ldg(&ss[f]);
            float W[4];
            #pragma unroll
            for (int c = 0; c < 4; c++) {
                int bi = j + c - 3;
                W[c] = (bi >= 0 && bi < 8) ? __ldg(&sw[f * 8 + bi]) * scale : 0.f;
            }
            const float S = 1.f / 6.f;
            v.x = (W[0] + 4.f * W[1] + W[2]) * S;
            v.y = (W[2] - W[0]) * 0.5f;
            v.z = (W[0] - 2.f * W[1] + W[2]) * 0.5f;
            v.w = (W[3] - W[0] + 3.f * (W[1] - W[2])) * S;
        }
        poly[t] = v;
    }
    float bwr[9];
    #pragma unroll
    for (int f = 0; f < 9; f++) bwr[f] = __ldg(&bw[f]);
    __syncthreads();

    // ---- spline value at x = 0 (padding pixels): cell j=5, u=0.5, silu=0 ----
    float Z[9];
    {
        const float4* pj = &poly[5 * 9];
        #pragma unroll
        for (int f = 0; f < 9; f++) {
            float4 a = pj[f];
            Z[f] = fmaf(fmaf(fmaf(a.w, 0.5f, a.z), 0.5f, a.y), 0.5f, a.x);
        }
    }

    const float* xcol = x   + img * 4096 + lane * 2;
    float*       ocol = out + img * 4096 + lane * 2;

    float accE[3] = {0.f, 0.f, 0.f};   // even column rolling accumulators
    float accO[3] = {0.f, 0.f, 0.f};   // odd  column rolling accumulators

    // v[f] = silu*bw[f] + cubic(u) with compile-time f
    auto evalf = [&](const float4* __restrict__ pj, float u, float s, int f) {
        float4 a = pj[f];
        float t = fmaf(a.w, u, a.z);
        t = fmaf(t, u, a.y);
        t = fmaf(t, u, a.x);
        return fmaf(s, bwr[f], t);
    };

    #pragma unroll
    for (int r = 0; r < NROWS; r++) {
        const int py = y0 - 1 + r;                 // pixel row
        float2 p = make_float2(0.f, 0.f);          // zero padding outside image
        if (py >= 0 && py < 64) p = *(const float2*)(xcol + py * 64);

        // per-pixel transform setup (even = col 2l, odd = col 2l+1)
        const float ve = p.x, vo = p.y;
        const float se = ve * __frcp_rn(1.f + __expf(-ve));
        const float so = vo * __frcp_rn(1.f + __expf(-vo));

        float xce = fmaf(ve, 2.5f, 5.5f);          // (v+2.2)/0.4
        float jfe = floorf(xce);
        float ue  = xce - jfe;
        int   je  = (int)jfe;
        if ((unsigned)je > 10u) { je = 11; ue = 0.f; }   // zero row

        float xco = fmaf(vo, 2.5f, 5.5f);
        float jfo = floorf(xco);
        float uo  = xco - jfo;
        int   jo  = (int)jfo;
        if ((unsigned)jo > 10u) { jo = 11; uo = 0.f; }

        const float4* pe = &poly[je * 9];
        const float4* po = &poly[jo * 9];

        // pixel col c serves out col c+1 (kw=0), c (kw=1), c-1 (kw=2);
        // pixel row py with kh serves out row py+1-kh -> slot [2-kh].
        float sendL[3], sendR[3];
        #pragma unroll
        for (int kh = 0; kh < 3; kh++) {
            accO[2 - kh] += evalf(pe, ue, se, kh * 3 + 0);  // even px -> own odd col
            accE[2 - kh] += evalf(pe, ue, se, kh * 3 + 1);  // even px -> own even col
            sendL[kh]     = evalf(pe, ue, se, kh * 3 + 2);  // even px -> lane-1 odd col
            sendR[kh]     = evalf(po, uo, so, kh * 3 + 0);  // odd  px -> lane+1 even col
            accO[2 - kh] += evalf(po, uo, so, kh * 3 + 1);
            accE[2 - kh] += evalf(po, uo, so, kh * 3 + 2);
        }

        // horizontal exchange; image-edge lanes receive the padding value Z
        #pragma unroll
        for (int kh = 0; kh < 3; kh++) {
            float rl = __shfl_down_sync(0xffffffffu, sendL[kh], 1);
            if (lane == 31) rl = Z[kh * 3 + 2];   // col 64 padding -> out col 63
            float rr = __shfl_up_sync(0xffffffffu, sendR[kh], 1);
            if (lane == 0)  rr = Z[kh * 3 + 0];   // col -1 padding -> out col 0
            accO[2 - kh] += rl;
            accE[2 - kh] += rr;
        }

        // out row py-1 complete after processing pixel row py
        if (r >= 2) {
            const int oy = y0 + r - 2;
            *(float2*)(ocol + oy * 64) = make_float2(accE[0], accO[0]);
        }
        accE[0] = accE[1]; accE[1] = accE[2]; accE[2] = 0.f;
        accO[0] = accO[1]; accO[1] = accO[2]; accO[2] = 0.f;
    }
}

extern "C" void kernel_launch(void* const* d_in, const int* in_sizes, int n_in,
                              void* d_out, int out_size) {
    const float* x  = (const float*)d_in[0];  // (8,32,64,64)
    const float* bw = (const float*)d_in[1];  // (1,9)
    const float* sw = (const float*)d_in[2];  // (1,9,8)
    const float* ss = (const float*)d_in[3];  // (1,9)
    float* out = (float*)d_out;

    // 256 images x 8 strips, one warp per strip
    kan_conv_kernel<<<2048, 32>>>(x, bw, sw, ss, out);
}